// round 14
// baseline (speedup 1.0000x reference)
#include <cuda_runtime.h>
#include <math.h>
#include <stdint.h>

#define Bb 2
#define Tt 512
#define Cc 256
#define Hh 8
#define Ee 32
#define NET 16
#define BT (Bb*Tt)      // 1024
#define C3 (3*Cc)       // 768
#define HNE (Hh*NET*Ee)

// ------- scratch (device globals: no allocation allowed) -------
__device__ float g_q[Bb*Hh*Tt*Ee];    // (b,h,t,e)
__device__ float g_k[Bb*Hh*Tt*Ee];
__device__ float g_v[Bb*Hh*Tt*Ee];
__device__ float g_ekt[2*HNE];        // 2 k-split partials
__device__ float g_evt[2*HNE];
__device__ float g_yn[2][BT*Cc];      // partial numerators (b,t,c), per j-part
__device__ float g_l[2][Bb*Hh*Tt];    // partial denominators, per j-part

// ---------------- cp.async helpers ----------------
__device__ __forceinline__ uint32_t smem_u32(const void* p) {
    uint32_t a;
    asm("{ .reg .u64 t; cvta.to.shared.u64 t, %1; cvt.u32.u64 %0, t; }"
        : "=r"(a) : "l"(p));
    return a;
}
__device__ __forceinline__ void cpa16(uint32_t dst, const void* src) {
    asm volatile("cp.async.ca.shared.global [%0], [%1], 16;" :: "r"(dst), "l"(src));
}
__device__ __forceinline__ void cpa4(uint32_t dst, const void* src) {
    asm volatile("cp.async.ca.shared.global [%0], [%1], 4;" :: "r"(dst), "l"(src));
}

// =====================================================================
// qkv GEMM: 32x64 tile, 128 threads, 4x4 micro, TK=16, double-buffered.
// grid (13, 32): bx 0..11 GEMM, bx==12 -> 32 edge-table blocks.  (proven)
// =====================================================================
__global__ void __launch_bounds__(128) gemm_qkv(const float* __restrict__ A,
                                                const float* __restrict__ Bm,
                                                const float* __restrict__ eet,
                                                const float* __restrict__ wek,
                                                const float* __restrict__ wev) {
    const int tid = threadIdx.x;

    if (blockIdx.x == 12) {
        // ---- edge-table partial: type t, k-half s, 2 cols/thread ----
        const int t = blockIdx.y >> 1, s = blockIdx.y & 1;
        __shared__ float ee[128];
        ee[tid] = eet[t * Cc + s * 128 + tid];
        __syncthreads();
        const int c0a = tid, c0b = tid + 128;
        const float* wkBase = wek + (size_t)(s * 128) * Cc;
        const float* wvBase = wev + (size_t)(s * 128) * Cc;
        float ska = 0.f, skb = 0.f, sva = 0.f, svb = 0.f;
        #pragma unroll 1
        for (int cb = 0; cb < 128; cb += 8) {
            float wka[8], wkb[8], wva[8], wvb[8];
            #pragma unroll
            for (int u = 0; u < 8; u++) {
                const float* wr = wkBase + (cb + u) * Cc;
                const float* vr = wvBase + (cb + u) * Cc;
                wka[u] = wr[c0a]; wkb[u] = wr[c0b];
                wva[u] = vr[c0a]; wvb[u] = vr[c0b];
            }
            #pragma unroll
            for (int u = 0; u < 8; u++) {
                float a = ee[cb + u];
                ska += a * wka[u]; skb += a * wkb[u];
                sva += a * wva[u]; svb += a * wvb[u];
            }
        }
        int ha = c0a >> 5, ea = c0a & 31;
        int hb = c0b >> 5, eb2 = c0b & 31;
        g_ekt[s * HNE + (ha * NET + t) * Ee + ea] = ska;
        g_ekt[s * HNE + (hb * NET + t) * Ee + eb2] = skb;
        g_evt[s * HNE + (ha * NET + t) * Ee + ea] = sva;
        g_evt[s * HNE + (hb * NET + t) * Ee + eb2] = svb;
        return;
    }

    __shared__ float As[2][16][36];   // k-major
    __shared__ float Bs[2][16][68];
    const int row0 = blockIdx.y * 32;
    const int col0 = blockIdx.x * 64;
    const int ar = tid >> 2, ac = (tid & 3) * 4;
    const int br = tid >> 4, bc = (tid & 15) * 4;
    const int tr = tid >> 4, tc = tid & 15;

    float4 arg, brg0, brg1;
    arg  = *(const float4*)&A[(row0 + ar) * Cc + ac];
    brg0 = *(const float4*)&Bm[br * C3 + col0 + bc];
    brg1 = *(const float4*)&Bm[(br + 8) * C3 + col0 + bc];
    As[0][ac+0][ar] = arg.x; As[0][ac+1][ar] = arg.y;
    As[0][ac+2][ar] = arg.z; As[0][ac+3][ar] = arg.w;
    *(float4*)&Bs[0][br][bc] = brg0;
    *(float4*)&Bs[0][br + 8][bc] = brg1;
    __syncthreads();

    float acc[4][4] = {};
    #pragma unroll 1
    for (int it = 0; it < 16; it++) {
        const int buf = it & 1;
        if (it < 15) {
            int k0 = (it + 1) * 16;
            arg  = *(const float4*)&A[(row0 + ar) * Cc + k0 + ac];
            brg0 = *(const float4*)&Bm[(k0 + br) * C3 + col0 + bc];
            brg1 = *(const float4*)&Bm[(k0 + br + 8) * C3 + col0 + bc];
        }
        #pragma unroll
        for (int kk = 0; kk < 16; kk++) {
            float4 a4 = *(const float4*)&As[buf][kk][tr * 4];
            float4 b4 = *(const float4*)&Bs[buf][kk][tc * 4];
            acc[0][0] += a4.x * b4.x; acc[0][1] += a4.x * b4.y;
            acc[0][2] += a4.x * b4.z; acc[0][3] += a4.x * b4.w;
            acc[1][0] += a4.y * b4.x; acc[1][1] += a4.y * b4.y;
            acc[1][2] += a4.y * b4.z; acc[1][3] += a4.y * b4.w;
            acc[2][0] += a4.z * b4.x; acc[2][1] += a4.z * b4.y;
            acc[2][2] += a4.z * b4.z; acc[2][3] += a4.z * b4.w;
            acc[3][0] += a4.w * b4.x; acc[3][1] += a4.w * b4.y;
            acc[3][2] += a4.w * b4.z; acc[3][3] += a4.w * b4.w;
        }
        if (it < 15) {
            const int nb = buf ^ 1;
            As[nb][ac+0][ar] = arg.x; As[nb][ac+1][ar] = arg.y;
            As[nb][ac+2][ar] = arg.z; As[nb][ac+3][ar] = arg.w;
            *(float4*)&Bs[nb][br][bc] = brg0;
            *(float4*)&Bs[nb][br + 8][bc] = brg1;
            __syncthreads();
        }
    }
    // fused reshape epilogue
    int colbase = col0 + tc * 4;
    int which = colbase >> 8;
    float* dstArr = (which == 0) ? g_q : (which == 1) ? g_k : g_v;
    int h = (colbase & 255) >> 5;
    int e = colbase & 31;
    #pragma unroll
    for (int u = 0; u < 4; u++) {
        int row = row0 + tr * 4 + u;
        int b = row >> 9, t = row & 511;
        *(float4*)&dstArr[(((b * Hh + h) * Tt) + t) * Ee + e] =
            make_float4(acc[u][0], acc[u][1], acc[u][2], acc[u][3]);
    }
}

// ==================== out = ((yn0+yn1)/(l0+l1)) @ w_proj: 32x32 tile ====================
__global__ void __launch_bounds__(128) gemm_out(const float* __restrict__ Bm,
                                                float* __restrict__ Cm) {
    __shared__ float As[2][16][36];   // k-major [kk][row]
    __shared__ float Bs[2][16][36];   // [kk][col]
    const int tid = threadIdx.x;
    const int row0 = blockIdx.y * 32;
    const int col0 = blockIdx.x * 32;
    const int ar = tid >> 2, ac = (tid & 3) * 4;
    const int br = tid >> 3, bc = (tid & 7) * 4;
    const int tr = tid >> 3, tc = tid & 7;

    const int arow = row0 + ar;            // global bt row
    const int ab = arow >> 9, at = arow & 511;

    // fused combine+divide A loader
    auto loadA = [&](int c0) -> float4 {
        int h = c0 >> 5;
        int lidx = (ab * Hh + h) * Tt + at;
        float ls = g_l[0][lidx] + g_l[1][lidx];
        float inv = __frcp_rn(ls);
        const float4 y0 = *(const float4*)&g_yn[0][arow * Cc + c0];
        const float4 y1 = *(const float4*)&g_yn[1][arow * Cc + c0];
        return make_float4((y0.x + y1.x) * inv, (y0.y + y1.y) * inv,
                           (y0.z + y1.z) * inv, (y0.w + y1.w) * inv);
    };

    float4 arg, brg;
    arg = loadA(ac);
    brg = *(const float4*)&Bm[br * Cc + col0 + bc];
    As[0][ac+0][ar] = arg.x; As[0][ac+1][ar] = arg.y;
    As[0][ac+2][ar] = arg.z; As[0][ac+3][ar] = arg.w;
    *(float4*)&Bs[0][br][bc] = brg;
    __syncthreads();

    float acc[2][4] = {};
    #pragma unroll 1
    for (int it = 0; it < 16; it++) {
        const int buf = it & 1;
        if (it < 15) {
            int k0 = (it + 1) * 16;
            arg = loadA(k0 + ac);
            brg = *(const float4*)&Bm[(k0 + br) * Cc + col0 + bc];
        }
        #pragma unroll
        for (int kk = 0; kk < 16; kk++) {
            float2 a2 = *(const float2*)&As[buf][kk][tr * 2];
            float4 b4 = *(const float4*)&Bs[buf][kk][tc * 4];
            acc[0][0] += a2.x * b4.x; acc[0][1] += a2.x * b4.y;
            acc[0][2] += a2.x * b4.z; acc[0][3] += a2.x * b4.w;
            acc[1][0] += a2.y * b4.x; acc[1][1] += a2.y * b4.y;
            acc[1][2] += a2.y * b4.z; acc[1][3] += a2.y * b4.w;
        }
        if (it < 15) {
            const int nb = buf ^ 1;
            As[nb][ac+0][ar] = arg.x; As[nb][ac+1][ar] = arg.y;
            As[nb][ac+2][ar] = arg.z; As[nb][ac+3][ar] = arg.w;
            *(float4*)&Bs[nb][br][bc] = brg;
            __syncthreads();
        }
    }
    #pragma unroll
    for (int u = 0; u < 2; u++)
        *(float4*)&Cm[(row0 + tr * 2 + u) * Cc + col0 + tc * 4] =
            make_float4(acc[u][0], acc[u][1], acc[u][2], acc[u][3]);
}

// ---------------- fused causal attention: split-j work units ----------------
// grid (64, H, B): bx -> (itile = 31 - bx/2, part = bx&1). Each i-tile's
// causal j-range splits into 2 independent halves; partials are additive
// (no max-tracking), combined in gemm_out. Max serial work: 8 tiles.
// smem layout (bytes): (identical to R11 best)
#define KS_OFF(buf)  ((buf) * 4096)            // float4[32*8] swizzled
#define VS_OFF(buf)  (8192 + (buf) * 4096)     // float4[32*8] swizzled
#define ET_OFF(buf)  (16384 + (buf) * 2176)    // int[32*17]
#define EB_OFF(buf)  (20736 + (buf) * 2304)    // int[16*36]
#define OFF_QEK  25344                         // float4[8*2*16*8] = 32768
#define OFF_EVT  58112                         // float[16*33]     = 2112
#define OFF_PE   60224                         // float4[8*32]     = 4096
#define OFF_BIAS 64320                         // float[16]
#define SMEM_ATTN 64384

__global__ void __launch_bounds__(256, 3) attn_kernel(const int* __restrict__ bm,
                                                      const float* __restrict__ abt) {
    extern __shared__ char sm[];
    float4* qek4  = (float4*)(sm + OFF_QEK);
    float*  qekf  = (float*) (sm + OFF_QEK);
    float*  evt_s = (float*) (sm + OFF_EVT);
    float4* pe_s  = (float4*)(sm + OFF_PE);
    float*  bias_s= (float*) (sm + OFF_BIAS);
    const uint32_t sbase = smem_u32(sm);

    const int b = blockIdx.z, h = blockIdx.y;
    const int tid = threadIdx.x;
    const int w = tid >> 5, lane = tid & 31;

    const int bx = blockIdx.x;                 // 0..63
    const int itile = 31 - (bx >> 1);          // heavy units first
    const int part = bx & 1;
    const int i0 = itile * 16;
    const int iA = i0 + w;
    const int iB = i0 + w + 8;
    const int nt = ((i0 + 15) >> 5) + 1;       // causal j-tiles for this i-tile
    const int halfn = (nt + 1) >> 1;
    const int tstart = part ? halfn : 0;
    const int tend   = part ? nt : halfn;

    const float* qb = g_q + (size_t)(b * Hh + h) * Tt * Ee;
    const float4* kb4 = (const float4*)(g_k + (size_t)(b * Hh + h) * Tt * Ee);
    const float4* vb4 = (const float4*)(g_v + (size_t)(b * Hh + h) * Tt * Ee);
    const int* bm_b = bm + (size_t)b * Tt * Tt;

    auto issue_tile = [&](int tile) {
        const int j0p = tile * 32;
        const int buf = tile & 1;
        const uint32_t ks = sbase + KS_OFF(buf), vs = sbase + VS_OFF(buf);
        const uint32_t et = sbase + ET_OFF(buf), eb = sbase + EB_OFF(buf);
        {
            int jj = tid >> 3, c4 = tid & 7;
            uint32_t sidx = (uint32_t)(jj * 8 + (c4 ^ (jj & 7))) * 16;
            cpa16(ks + sidx, &kb4[(j0p + jj) * 8 + c4]);
            cpa16(vs + sidx, &vb4[(j0p + jj) * 8 + c4]);
        }
        #pragma unroll
        for (int x = tid; x < 512; x += 256) {
            int jj = x >> 4, iw = x & 15;
            cpa4(et + (uint32_t)(jj * 17 + iw) * 4,
                 &bm_b[(j0p + jj) * Tt + i0 + iw]);
        }
        if (tid < 128) {
            int iw = tid >> 3, g = tid & 7;
            cpa16(eb + (uint32_t)(iw * 36 + g * 4) * 4,
                  &bm_b[(i0 + iw) * Tt + j0p + g * 4]);
        }
        asm volatile("cp.async.commit_group;" ::: "memory");
    };
    if (tstart < tend) issue_tile(tstart);

    // ---- preamble (overlaps first tile loads) ----
    for (int x = tid; x < NET * Ee; x += 256)
        evt_s[(x >> 5) * 33 + (x & 31)] = g_evt[h * NET * Ee + x] + g_evt[HNE + h * NET * Ee + x];
    if (tid < NET) bias_s[tid] = abt[tid * Hh + h];
    {
        float qA = qb[iA * Ee + lane];
        float qB = qb[iB * Ee + lane];
        int swzbase = lane >> 2;
        #pragma unroll
        for (int t = 0; t < NET; t++) {
            int idx = (h * NET + t) * Ee + lane;
            float ek = g_ekt[idx] + g_ekt[HNE + idx];
            int swz = ((swzbase ^ (t & 7)) << 2) | (lane & 3);
            qekf[((w * 2 + 0) * 16 + t) * 32 + swz] = qA * ek;
            qekf[((w * 2 + 1) * 16 + t) * 32 + swz] = qB * ek;
        }
    }

    float lA = 0.f, lB = 0.f;
    float accA[4] = {}, accB[4] = {};
    const float inv_scale = 0.1767766952966369f;   // 1/sqrt(32)

    for (int tile = tstart; tile < tend; tile++) {
        const int j0 = tile * 32;
        const int buf = tile & 1;
        asm volatile("cp.async.wait_group 0;" ::: "memory");
        __syncthreads();
        if (tile + 1 < tend) issue_tile(tile + 1);

        const float4* ks4 = (const float4*)(sm + KS_OFF(buf));
        const float*  v_sf= (const float*) (sm + VS_OFF(buf));
        const int*    et_s= (const int*)   (sm + ET_OFF(buf));
        const int*    eb_s= (const int*)   (sm + EB_OFF(buf));

        // ---- phase 1: lane = j ----
        const int jg = j0 + lane;
        const int etA = et_s[lane * 17 + w];
        const int etB = et_s[lane * 17 + w + 8];
        const float4* krow = ks4 + lane * 8;
        const int kx = lane & 7;
        const float4* qrA = qek4 + ((w * 2 + 0) * 16 + etA) * 8;
        const float4* qrB = qek4 + ((w * 2 + 1) * 16 + etB) * 8;
        const int qxA = etA & 7, qxB = etB & 7;
        float4 aA = {0,0,0,0}, aB = {0,0,0,0};
        #pragma unroll
        for (int c = 0; c < 8; c++) {
            float4 k4 = krow[c ^ kx];
            float4 qa = qrA[c ^ qxA];
            float4 qc = qrB[c ^ qxB];
            aA.x += qa.x * k4.x; aA.y += qa.y * k4.y;
            aA.z += qa.z * k4.z; aA.w += qa.w * k4.w;
            aB.x += qc.x * k4.x; aB.y += qc.y * k4.y;
            aB.z += qc.z * k4.z; aB.w += qc.w * k4.w;
        }
        float dA = (aA.x + aA.y) + (aA.z + aA.w);
        float dB = (aB.x + aB.y) + (aB.z + aB.w);
        float bA = bias_s[eb_s[w * 36 + lane]];
        float bB = bias_s[eb_s[(w + 8) * 36 + lane]];
        float sA = (jg <= iA) ? dA * inv_scale + bA : -INFINITY;
        float sB = (jg <= iB) ? dB * inv_scale + bB : -INFINITY;

        // ---- absolute softmax numerators (scores bounded) ----
        float pA = __expf(sA);
        float pB = __expf(sB);
        lA += pA; lB += pB;

        float4* pw = pe_s + w * 32;
        pw[lane] = make_float4(pA, __int_as_float(etA * 132),
                               pB, __int_as_float(etB * 132));
        __syncwarp();

        // ---- phase 2: lane = e ----
        int jlim = iB - j0 + 1; if (jlim > 32) jlim = 32;
        int jlim8 = (jlim + 7) & ~7;
        const char* evb = (const char*)evt_s + lane * 4;
        const int le_hi = (lane >> 2), le_lo = (lane & 3);
        for (int j8 = 0; j8 < jlim8; j8 += 8) {
            #pragma unroll
            for (int u = 0; u < 8; u++) {
                float4 pe = pw[j8 + u];
                float vv = v_sf[(j8 + u) * 32 + ((le_hi ^ u) << 2) + le_lo];
                float evA = *(const float*)(evb + __float_as_int(pe.y));
                float evB = *(const float*)(evb + __float_as_int(pe.w));
                accA[u & 3] += (pe.x * vv) * evA;
                accB[u & 3] += (pe.z * vv) * evB;
            }
        }
    }
    // lane-local denominator reduction (once)
    float lAs = lA, lBs = lB;
    #pragma unroll
    for (int o = 16; o; o >>= 1) {
        lAs += __shfl_xor_sync(0xffffffffu, lAs, o);
        lBs += __shfl_xor_sync(0xffffffffu, lBs, o);
    }
    // write partials (NOT divided); zero when this part had no tiles
    float sA = ((accA[0] + accA[1]) + (accA[2] + accA[3]));
    float sB = ((accB[0] + accB[1]) + (accB[2] + accB[3]));
    g_yn[part][(size_t)(b * Tt + iA) * Cc + h * Ee + lane] = sA;
    g_yn[part][(size_t)(b * Tt + iB) * Cc + h * Ee + lane] = sB;
    if (lane == 0) {
        int lbase = (b * Hh + h) * Tt;
        g_l[part][lbase + iA] = lAs;
        g_l[part][lbase + iB] = lBs;
    }
}

// ---------------- launch ----------------
extern "C" void kernel_launch(void* const* d_in, const int* in_sizes, int n_in,
                              void* d_out, int out_size) {
    const float* x      = (const float*)d_in[0];
    const int*   bm     = (const int*)d_in[1];
    const float* w_attn = (const float*)d_in[2];
    const float* w_proj = (const float*)d_in[3];
    const float* w_ek   = (const float*)d_in[4];
    const float* w_ev   = (const float*)d_in[5];
    const float* eet    = (const float*)d_in[6];
    const float* abt    = (const float*)d_in[7];
    float* out = (float*)d_out;

    cudaFuncSetAttribute(attn_kernel, cudaFuncAttributeMaxDynamicSharedMemorySize, SMEM_ATTN);

    // qkv GEMM (bx 0..11) + edge-table blocks (bx==12)
    gemm_qkv<<<dim3(13, BT / 32), 128>>>(x, w_attn, eet, w_ek, w_ev);
    // fused attention, split-j work units -> partial (yn, l)
    attn_kernel<<<dim3(64, Hh, Bb), 256, SMEM_ATTN>>>(bm, abt);
    // out = ((yn0+yn1)/(l0+l1)) @ w_proj
    gemm_out<<<dim3(Cc / 32, BT / 32), 128>>>(w_proj, out);
}

// round 15
// speedup vs baseline: 1.1271x; 1.1271x over previous
#include <cuda_runtime.h>
#include <math.h>
#include <stdint.h>

#define Bb 2
#define Tt 512
#define Cc 256
#define Hh 8
#define Ee 32
#define NET 16
#define BT (Bb*Tt)      // 1024
#define C3 (3*Cc)       // 768
#define HNE (Hh*NET*Ee)

// ------- scratch (device globals: no allocation allowed) -------
__device__ float g_q[Bb*Hh*Tt*Ee];    // (b,h,t,e)
__device__ float g_k[Bb*Hh*Tt*Ee];
__device__ float g_v[Bb*Hh*Tt*Ee];
__device__ float g_ekt[2*HNE];        // 2 k-split partials
__device__ float g_evt[2*HNE];
__device__ float g_y[BT*Cc];          // (b,t,c) pre-proj

// ---------------- cp.async helpers ----------------
__device__ __forceinline__ uint32_t smem_u32(const void* p) {
    uint32_t a;
    asm("{ .reg .u64 t; cvta.to.shared.u64 t, %1; cvt.u32.u64 %0, t; }"
        : "=r"(a) : "l"(p));
    return a;
}
__device__ __forceinline__ void cpa16(uint32_t dst, const void* src) {
    asm volatile("cp.async.ca.shared.global [%0], [%1], 16;" :: "r"(dst), "l"(src));
}
__device__ __forceinline__ void cpa4(uint32_t dst, const void* src) {
    asm volatile("cp.async.ca.shared.global [%0], [%1], 4;" :: "r"(dst), "l"(src));
}

// =====================================================================
// qkv GEMM: 32x64 tile, 128 threads, 4x4 micro, TK=32, double-buffered.
// grid (13, 32): bx 0..11 GEMM, bx==12 -> 32 edge-table blocks.
// =====================================================================
__global__ void __launch_bounds__(128) gemm_qkv(const float* __restrict__ A,
                                                const float* __restrict__ Bm,
                                                const float* __restrict__ eet,
                                                const float* __restrict__ wek,
                                                const float* __restrict__ wev) {
    const int tid = threadIdx.x;

    if (blockIdx.x == 12) {
        // ---- edge-table partial: type t, k-half s, 2 cols/thread ----
        const int t = blockIdx.y >> 1, s = blockIdx.y & 1;
        __shared__ float ee[128];
        ee[tid] = eet[t * Cc + s * 128 + tid];
        __syncthreads();
        const int c0a = tid, c0b = tid + 128;
        const float* wkBase = wek + (size_t)(s * 128) * Cc;
        const float* wvBase = wev + (size_t)(s * 128) * Cc;
        float ska = 0.f, skb = 0.f, sva = 0.f, svb = 0.f;
        #pragma unroll 1
        for (int cb = 0; cb < 128; cb += 8) {
            float wka[8], wkb[8], wva[8], wvb[8];
            #pragma unroll
            for (int u = 0; u < 8; u++) {
                const float* wr = wkBase + (cb + u) * Cc;
                const float* vr = wvBase + (cb + u) * Cc;
                wka[u] = wr[c0a]; wkb[u] = wr[c0b];
                wva[u] = vr[c0a]; wvb[u] = vr[c0b];
            }
            #pragma unroll
            for (int u = 0; u < 8; u++) {
                float a = ee[cb + u];
                ska += a * wka[u]; skb += a * wkb[u];
                sva += a * wva[u]; svb += a * wvb[u];
            }
        }
        int ha = c0a >> 5, ea = c0a & 31;
        int hb = c0b >> 5, eb2 = c0b & 31;
        g_ekt[s * HNE + (ha * NET + t) * Ee + ea] = ska;
        g_ekt[s * HNE + (hb * NET + t) * Ee + eb2] = skb;
        g_evt[s * HNE + (ha * NET + t) * Ee + ea] = sva;
        g_evt[s * HNE + (hb * NET + t) * Ee + eb2] = svb;
        return;
    }

    __shared__ float As[2][32][36];   // k-major [kk][row]
    __shared__ float Bs[2][32][68];   // [kk][col]
    const int row0 = blockIdx.y * 32;
    const int col0 = blockIdx.x * 64;
    const int ar = tid >> 2, ac = (tid & 3) * 4;   // A: 2 f4/thread (k, k+16)
    const int br = tid >> 4, bc = (tid & 15) * 4;  // B: 4 f4/thread (rows +0,8,16,24)
    const int tr = tid >> 4, tc = tid & 15;        // micro 4x4

    float4 arg0, arg1, brg[4];
    auto loadG = [&](int k0) {
        arg0 = *(const float4*)&A[(row0 + ar) * Cc + k0 + ac];
        arg1 = *(const float4*)&A[(row0 + ar) * Cc + k0 + 16 + ac];
        #pragma unroll
        for (int p = 0; p < 4; p++)
            brg[p] = *(const float4*)&Bm[(k0 + br + p * 8) * C3 + col0 + bc];
    };
    auto storeS = [&](int nb) {
        As[nb][ac+0][ar] = arg0.x; As[nb][ac+1][ar] = arg0.y;
        As[nb][ac+2][ar] = arg0.z; As[nb][ac+3][ar] = arg0.w;
        As[nb][16+ac+0][ar] = arg1.x; As[nb][16+ac+1][ar] = arg1.y;
        As[nb][16+ac+2][ar] = arg1.z; As[nb][16+ac+3][ar] = arg1.w;
        #pragma unroll
        for (int p = 0; p < 4; p++)
            *(float4*)&Bs[nb][br + p * 8][bc] = brg[p];
    };

    loadG(0);
    storeS(0);
    __syncthreads();

    float acc[4][4] = {};
    #pragma unroll 1
    for (int it = 0; it < 8; it++) {
        const int buf = it & 1;
        if (it < 7) loadG((it + 1) * 32);
        #pragma unroll
        for (int kk = 0; kk < 32; kk++) {
            float4 a4 = *(const float4*)&As[buf][kk][tr * 4];
            float4 b4 = *(const float4*)&Bs[buf][kk][tc * 4];
            acc[0][0] += a4.x * b4.x; acc[0][1] += a4.x * b4.y;
            acc[0][2] += a4.x * b4.z; acc[0][3] += a4.x * b4.w;
            acc[1][0] += a4.y * b4.x; acc[1][1] += a4.y * b4.y;
            acc[1][2] += a4.y * b4.z; acc[1][3] += a4.y * b4.w;
            acc[2][0] += a4.z * b4.x; acc[2][1] += a4.z * b4.y;
            acc[2][2] += a4.z * b4.z; acc[2][3] += a4.z * b4.w;
            acc[3][0] += a4.w * b4.x; acc[3][1] += a4.w * b4.y;
            acc[3][2] += a4.w * b4.z; acc[3][3] += a4.w * b4.w;
        }
        if (it < 7) {
            storeS(buf ^ 1);
            __syncthreads();
        }
    }
    // fused reshape epilogue
    int colbase = col0 + tc * 4;
    int which = colbase >> 8;
    float* dstArr = (which == 0) ? g_q : (which == 1) ? g_k : g_v;
    int h = (colbase & 255) >> 5;
    int e = colbase & 31;
    #pragma unroll
    for (int u = 0; u < 4; u++) {
        int row = row0 + tr * 4 + u;
        int b = row >> 9, t = row & 511;
        *(float4*)&dstArr[(((b * Hh + h) * Tt) + t) * Ee + e] =
            make_float4(acc[u][0], acc[u][1], acc[u][2], acc[u][3]);
    }
}

// ==================== out = g_y @ w_proj: 32x32 tile, TK=32, 256 blocks ====================
__global__ void __launch_bounds__(128) gemm_out(const float* __restrict__ A,
                                                const float* __restrict__ Bm,
                                                float* __restrict__ Cm) {
    __shared__ float As[2][32][36];   // k-major [kk][row]
    __shared__ float Bs[2][32][36];   // [kk][col]
    const int tid = threadIdx.x;
    const int row0 = blockIdx.y * 32;
    const int col0 = blockIdx.x * 32;
    const int ar = tid >> 2, ac = (tid & 3) * 4;   // A: 2 f4/thread (k, k+16)
    const int br = tid >> 3, bc = (tid & 7) * 4;   // B: 2 f4/thread (rows +0, +16)
    const int tr = tid >> 3, tc = tid & 7;         // micro 2x4

    float4 arg0, arg1, brg0, brg1;
    auto loadG = [&](int k0) {
        arg0 = *(const float4*)&A[(row0 + ar) * Cc + k0 + ac];
        arg1 = *(const float4*)&A[(row0 + ar) * Cc + k0 + 16 + ac];
        brg0 = *(const float4*)&Bm[(k0 + br) * Cc + col0 + bc];
        brg1 = *(const float4*)&Bm[(k0 + br + 16) * Cc + col0 + bc];
    };
    auto storeS = [&](int nb) {
        As[nb][ac+0][ar] = arg0.x; As[nb][ac+1][ar] = arg0.y;
        As[nb][ac+2][ar] = arg0.z; As[nb][ac+3][ar] = arg0.w;
        As[nb][16+ac+0][ar] = arg1.x; As[nb][16+ac+1][ar] = arg1.y;
        As[nb][16+ac+2][ar] = arg1.z; As[nb][16+ac+3][ar] = arg1.w;
        *(float4*)&Bs[nb][br][bc] = brg0;
        *(float4*)&Bs[nb][br + 16][bc] = brg1;
    };

    loadG(0);
    storeS(0);
    __syncthreads();

    float acc[2][4] = {};
    #pragma unroll 1
    for (int it = 0; it < 8; it++) {
        const int buf = it & 1;
        if (it < 7) loadG((it + 1) * 32);
        #pragma unroll
        for (int kk = 0; kk < 32; kk++) {
            float2 a2 = *(const float2*)&As[buf][kk][tr * 2];
            float4 b4 = *(const float4*)&Bs[buf][kk][tc * 4];
            acc[0][0] += a2.x * b4.x; acc[0][1] += a2.x * b4.y;
            acc[0][2] += a2.x * b4.z; acc[0][3] += a2.x * b4.w;
            acc[1][0] += a2.y * b4.x; acc[1][1] += a2.y * b4.y;
            acc[1][2] += a2.y * b4.z; acc[1][3] += a2.y * b4.w;
        }
        if (it < 7) {
            storeS(buf ^ 1);
            __syncthreads();
        }
    }
    #pragma unroll
    for (int u = 0; u < 2; u++)
        *(float4*)&Cm[(row0 + tr * 2 + u) * Cc + col0 + tc * 4] =
            make_float4(acc[u][0], acc[u][1], acc[u][2], acc[u][3]);
}

// ---------------- fused causal attention (R11 proven, byte-identical) ----------------
#define KS_OFF(buf)  ((buf) * 4096)            // float4[32*8] swizzled
#define VS_OFF(buf)  (8192 + (buf) * 4096)     // float4[32*8] swizzled
#define ET_OFF(buf)  (16384 + (buf) * 2176)    // int[32*17]
#define EB_OFF(buf)  (20736 + (buf) * 2304)    // int[16*36]
#define OFF_QEK  25344                         // float4[8*2*16*8] = 32768
#define OFF_EVT  58112                         // float[16*33]     = 2112
#define OFF_PE   60224                         // float4[8*32]     = 4096
#define OFF_BIAS 64320                         // float[16]
#define SMEM_ATTN 64384

__global__ void __launch_bounds__(256, 3) attn_kernel(const int* __restrict__ bm,
                                                      const float* __restrict__ abt) {
    extern __shared__ char sm[];
    float4* qek4  = (float4*)(sm + OFF_QEK);
    float*  qekf  = (float*) (sm + OFF_QEK);
    float*  evt_s = (float*) (sm + OFF_EVT);
    float4* pe_s  = (float4*)(sm + OFF_PE);
    float*  bias_s= (float*) (sm + OFF_BIAS);
    const uint32_t sbase = smem_u32(sm);

    const int b = blockIdx.z, h = blockIdx.y;
    const int tid = threadIdx.x;
    const int w = tid >> 5, lane = tid & 31;
    const int itile = gridDim.x - 1 - blockIdx.x;   // heavy tiles first
    const int i0 = itile * 16;
    const int iA = i0 + w;
    const int iB = i0 + w + 8;
    const int ntiles = ((i0 + 15) >> 5) + 1;

    const float* qb = g_q + (size_t)(b * Hh + h) * Tt * Ee;
    const float4* kb4 = (const float4*)(g_k + (size_t)(b * Hh + h) * Tt * Ee);
    const float4* vb4 = (const float4*)(g_v + (size_t)(b * Hh + h) * Tt * Ee);
    const int* bm_b = bm + (size_t)b * Tt * Tt;

    auto issue_tile = [&](int tile) {
        const int j0p = tile * 32;
        const int buf = tile & 1;
        const uint32_t ks = sbase + KS_OFF(buf), vs = sbase + VS_OFF(buf);
        const uint32_t et = sbase + ET_OFF(buf), eb = sbase + EB_OFF(buf);
        {
            int jj = tid >> 3, c4 = tid & 7;
            uint32_t sidx = (uint32_t)(jj * 8 + (c4 ^ (jj & 7))) * 16;
            cpa16(ks + sidx, &kb4[(j0p + jj) * 8 + c4]);
            cpa16(vs + sidx, &vb4[(j0p + jj) * 8 + c4]);
        }
        #pragma unroll
        for (int x = tid; x < 512; x += 256) {
            int jj = x >> 4, iw = x & 15;
            cpa4(et + (uint32_t)(jj * 17 + iw) * 4,
                 &bm_b[(j0p + jj) * Tt + i0 + iw]);
        }
        if (tid < 128) {
            int iw = tid >> 3, g = tid & 7;
            cpa16(eb + (uint32_t)(iw * 36 + g * 4) * 4,
                  &bm_b[(i0 + iw) * Tt + j0p + g * 4]);
        }
        asm volatile("cp.async.commit_group;" ::: "memory");
    };
    issue_tile(0);

    // ---- preamble (overlaps tile-0 loads) ----
    for (int x = tid; x < NET * Ee; x += 256)
        evt_s[(x >> 5) * 33 + (x & 31)] = g_evt[h * NET * Ee + x] + g_evt[HNE + h * NET * Ee + x];
    if (tid < NET) bias_s[tid] = abt[tid * Hh + h];
    {
        float qA = qb[iA * Ee + lane];
        float qB = qb[iB * Ee + lane];
        int swzbase = lane >> 2;
        #pragma unroll
        for (int t = 0; t < NET; t++) {
            int idx = (h * NET + t) * Ee + lane;
            float ek = g_ekt[idx] + g_ekt[HNE + idx];
            int swz = ((swzbase ^ (t & 7)) << 2) | (lane & 3);
            qekf[((w * 2 + 0) * 16 + t) * 32 + swz] = qA * ek;
            qekf[((w * 2 + 1) * 16 + t) * 32 + swz] = qB * ek;
        }
    }

    float lA = 0.f, lB = 0.f;
    float accA[4] = {}, accB[4] = {};
    const float inv_scale = 0.1767766952966369f;   // 1/sqrt(32)

    for (int tile = 0; tile < ntiles; tile++) {
        const int j0 = tile * 32;
        const int buf = tile & 1;
        asm volatile("cp.async.wait_group 0;" ::: "memory");
        __syncthreads();
        if (tile + 1 < ntiles) issue_tile(tile + 1);

        const float4* ks4 = (const float4*)(sm + KS_OFF(buf));
        const float*  v_sf= (const float*) (sm + VS_OFF(buf));
        const int*    et_s= (const int*)   (sm + ET_OFF(buf));
        const int*    eb_s= (const int*)   (sm + EB_OFF(buf));

        // ---- phase 1: lane = j ----
        const int jg = j0 + lane;
        const int etA = et_s[lane * 17 + w];
        const int etB = et_s[lane * 17 + w + 8];
        const float4* krow = ks4 + lane * 8;
        const int kx = lane & 7;
        const float4* qrA = qek4 + ((w * 2 + 0) * 16 + etA) * 8;
        const float4* qrB = qek4 + ((w * 2 + 1) * 16 + etB) * 8;
        const int qxA = etA & 7, qxB = etB & 7;
        float4 aA = {0,0,0,0}, aB = {0,0,0,0};
        #pragma unroll
        for (int c = 0; c < 8; c++) {
            float4 k4 = krow[c ^ kx];
            float4 qa = qrA[c ^ qxA];
            float4 qc = qrB[c ^ qxB];
            aA.x += qa.x * k4.x; aA.y += qa.y * k4.y;
            aA.z += qa.z * k4.z; aA.w += qa.w * k4.w;
            aB.x += qc.x * k4.x; aB.y += qc.y * k4.y;
            aB.z += qc.z * k4.z; aB.w += qc.w * k4.w;
        }
        float dA = (aA.x + aA.y) + (aA.z + aA.w);
        float dB = (aB.x + aB.y) + (aB.z + aB.w);
        float bA = bias_s[eb_s[w * 36 + lane]];
        float bB = bias_s[eb_s[(w + 8) * 36 + lane]];
        float sA = (jg <= iA) ? dA * inv_scale + bA : -INFINITY;
        float sB = (jg <= iB) ? dB * inv_scale + bB : -INFINITY;

        // ---- absolute softmax numerators (scores bounded) ----
        float pA = __expf(sA);
        float pB = __expf(sB);
        lA += pA; lB += pB;

        float4* pw = pe_s + w * 32;
        pw[lane] = make_float4(pA, __int_as_float(etA * 132),
                               pB, __int_as_float(etB * 132));
        __syncwarp();

        // ---- phase 2: lane = e ----
        int jlim = iB - j0 + 1; if (jlim > 32) jlim = 32;
        int jlim8 = (jlim + 7) & ~7;
        const char* evb = (const char*)evt_s + lane * 4;
        const int le_hi = (lane >> 2), le_lo = (lane & 3);
        for (int j8 = 0; j8 < jlim8; j8 += 8) {
            #pragma unroll
            for (int u = 0; u < 8; u++) {
                float4 pe = pw[j8 + u];
                float vv = v_sf[(j8 + u) * 32 + ((le_hi ^ u) << 2) + le_lo];
                float evA = *(const float*)(evb + __float_as_int(pe.y));
                float evB = *(const float*)(evb + __float_as_int(pe.w));
                accA[u & 3] += (pe.x * vv) * evA;
                accB[u & 3] += (pe.z * vv) * evB;
            }
        }
    }
    float lAs = lA, lBs = lB;
    #pragma unroll
    for (int o = 16; o; o >>= 1) {
        lAs += __shfl_xor_sync(0xffffffffu, lAs, o);
        lBs += __shfl_xor_sync(0xffffffffu, lBs, o);
    }
    float oA = ((accA[0] + accA[1]) + (accA[2] + accA[3])) / lAs;
    float oB = ((accB[0] + accB[1]) + (accB[2] + accB[3])) / lBs;
    g_y[(size_t)(b * Tt + iA) * Cc + h * Ee + lane] = oA;
    g_y[(size_t)(b * Tt + iB) * Cc + h * Ee + lane] = oB;
}

// ---------------- launch ----------------
extern "C" void kernel_launch(void* const* d_in, const int* in_sizes, int n_in,
                              void* d_out, int out_size) {
    const float* x      = (const float*)d_in[0];
    const int*   bm     = (const int*)d_in[1];
    const float* w_attn = (const float*)d_in[2];
    const float* w_proj = (const float*)d_in[3];
    const float* w_ek   = (const float*)d_in[4];
    const float* w_ev   = (const float*)d_in[5];
    const float* eet    = (const float*)d_in[6];
    const float* abt    = (const float*)d_in[7];
    float* out = (float*)d_out;

    float* gy; cudaGetSymbolAddress((void**)&gy, g_y);

    cudaFuncSetAttribute(attn_kernel, cudaFuncAttributeMaxDynamicSharedMemorySize, SMEM_ATTN);

    // qkv GEMM (bx 0..11) + edge-table blocks (bx==12)
    gemm_qkv<<<dim3(13, BT / 32), 128>>>(x, w_attn, eet, w_ek, w_ev);
    // fused attention -> g_y (b,t,c)
    attn_kernel<<<dim3(Tt / 16, Hh, Bb), 256, SMEM_ATTN>>>(bm, abt);
    // out = y @ w_proj
    gemm_out<<<dim3(Cc / 32, BT / 32), 128>>>(gy, w_proj, out);
}